// round 1
// baseline (speedup 1.0000x reference)
#include <cuda_runtime.h>
#include <math.h>

// DistanceRelativeBias: out[b,k,i,j] = f_k(||c_i - c_j||)
// f_k(d) = b2[k] + sum_h silu(d*w1[h] + b1[h]) * w2[h][k]
// Strategy: per-head piecewise-linear table (value,slope) in shared memory,
// built once per persistent block; main loop = distance + table lerp + wide stores.

#define NB    4
#define NPT   1024
#define HID   64
#define HEADS 16
#define TE    1024          // table entries
#define DMAX_ 16.0f         // table covers d in [0, 16)

static __device__ __forceinline__ float silu_f(float x) {
    return x / (1.0f + expf(-x));
}

__global__ __launch_bounds__(1024, 1)
void drb_kernel(const float* __restrict__ coords,
                const float* __restrict__ w1,
                const float* __restrict__ b1,
                const float* __restrict__ w2,
                const float* __restrict__ b2,
                float* __restrict__ out,
                int ngroups)
{
    // T[k][p] : .x = f_k(p*delta)  (p in 0..TE, so slot TE holds endpoint value)
    //           .y = f_k((p+1)*delta) - f_k(p*delta)  (p in 0..TE-1)
    // Row stride TE+1 (odd) spreads banks.
    extern __shared__ float2 T[];
    const int tid = threadIdx.x;
    const float delta = DMAX_ / (float)TE;

    // ---- Phase 1: table values ----
    for (int p = tid; p <= TE; p += blockDim.x) {
        float dv = (float)p * delta;
        float acc[HEADS];
        #pragma unroll
        for (int k = 0; k < HEADS; k++) acc[k] = b2[k];
        #pragma unroll 4
        for (int h = 0; h < HID; h++) {
            float x = fmaf(dv, w1[h], b1[h]);
            float s = silu_f(x);
            const float* w2r = w2 + h * HEADS;
            #pragma unroll
            for (int k = 0; k < HEADS; k++) acc[k] = fmaf(s, w2r[k], acc[k]);
        }
        #pragma unroll
        for (int k = 0; k < HEADS; k++) T[k * (TE + 1) + p].x = acc[k];
    }
    __syncthreads();

    // ---- Phase 2: slopes ----
    for (int p = tid; p < TE; p += blockDim.x) {
        #pragma unroll
        for (int k = 0; k < HEADS; k++) {
            float2* row = T + k * (TE + 1);
            row[p].y = row[p + 1].x - row[p].x;
        }
    }
    __syncthreads();

    // ---- Phase 3: main loop. One thread = 4 consecutive j (float4 store per head) ----
    const float scale = (float)TE / DMAX_;
    const float tmax  = (float)TE - 0.001f;
    for (int g = blockIdx.x * blockDim.x + tid; g < ngroups; g += gridDim.x * blockDim.x) {
        int b  = g >> 18;               // NPT*NPT/4 = 262144 = 2^18 groups per batch
        int r  = g & 262143;
        int i  = r >> 8;                // 256 groups (of 4 j's) per row
        int j0 = (r & 255) << 2;

        const float* cb = coords + b * (NPT * 3);
        float cix = cb[3 * i + 0];
        float ciy = cb[3 * i + 1];
        float ciz = cb[3 * i + 2];

        int   idx[4];
        float fr[4];
        #pragma unroll
        for (int u = 0; u < 4; u++) {
            const float* cj = cb + 3 * (j0 + u);
            float dx = cix - cj[0];
            float dy = ciy - cj[1];
            float dz = ciz - cj[2];
            float sq = fmaf(dx, dx, fmaf(dy, dy, dz * dz));
            float d  = sqrtf(sq);
            float t  = fminf(d * scale, tmax);
            int  id  = (int)t;
            idx[u] = id;
            fr[u]  = t - (float)id;
        }

        float* ob = out + (((size_t)(b * HEADS)) << 20) + ((size_t)i << 10) + j0;
        #pragma unroll
        for (int k = 0; k < HEADS; k++) {
            const float2* row = T + k * (TE + 1);
            float2 a0 = row[idx[0]];
            float2 a1 = row[idx[1]];
            float2 a2 = row[idx[2]];
            float2 a3 = row[idx[3]];
            float4 v;
            v.x = fmaf(fr[0], a0.y, a0.x);
            v.y = fmaf(fr[1], a1.y, a1.x);
            v.z = fmaf(fr[2], a2.y, a2.x);
            v.w = fmaf(fr[3], a3.y, a3.x);
            *reinterpret_cast<float4*>(ob + ((size_t)k << 20)) = v;
        }
    }
}

extern "C" void kernel_launch(void* const* d_in, const int* in_sizes, int n_in,
                              void* d_out, int out_size)
{
    const float* coords = (const float*)d_in[0];
    const float* w1     = (const float*)d_in[1];
    const float* b1     = (const float*)d_in[2];
    const float* w2     = (const float*)d_in[3];
    const float* b2     = (const float*)d_in[4];
    float* out = (float*)d_out;

    const int smem_bytes = HEADS * (TE + 1) * (int)sizeof(float2);   // 131,200 B
    cudaFuncSetAttribute(drb_kernel, cudaFuncAttributeMaxDynamicSharedMemorySize, smem_bytes);

    int nsm = 148;
    cudaDeviceGetAttribute(&nsm, cudaDevAttrMultiProcessorCount, 0);

    const int ngroups = NB * NPT * (NPT / 4);   // 1,048,576
    drb_kernel<<<nsm, 1024, smem_bytes>>>(coords, w1, b1, w2, b2, out, ngroups);
}

// round 3
// speedup vs baseline: 1.2131x; 1.2131x over previous
#include <cuda_runtime.h>
#include <cuda_fp16.h>
#include <math.h>

// DistanceRelativeBias: out[b,k,i,j] = f_k(||c_i - c_j||)
// f_k(d) = b2[k] + sum_h silu(d*w1[h] + b1[h]) * w2[h][k]
//
// R3 (= R2 re-bench; infra failure last round): per-point piecewise-linear
// table packed half2(value, slope), point-major rows of 16 heads (64B data,
// padded to 80B so random rows spread across quad-banks). Lookup = 4x LDS.128
// per point. Streaming stores for the 256MB write-once output.

#define NB    4
#define NPT   1024
#define HID   64
#define HEADS 16
#define TE    1024          // table intervals
#define DMAX_ 16.0f
#define ROW_U32 20          // 16 half2 + 4 pad = 80 bytes per row

// dynamic smem layout:
//   [0, TE*ROW_U32) u32                   : packed table (u32 = half2)
//   scratch (fp32 values) at SCR_OFF      : (TE+1) x HEADS floats
#define SCR_OFF (TE * ROW_U32)

static __device__ __forceinline__ float silu_f(float x) {
    return x / (1.0f + __expf(-x));
}

__global__ __launch_bounds__(1024, 1)
void drb_kernel(const float* __restrict__ coords,
                const float* __restrict__ w1,
                const float* __restrict__ b1,
                const float* __restrict__ w2,
                const float* __restrict__ b2,
                float* __restrict__ out,
                int ngroups)
{
    extern __shared__ unsigned int tab[];
    float* scratch = reinterpret_cast<float*>(tab + SCR_OFF);

    const int tid = threadIdx.x;
    const float delta = DMAX_ / (float)TE;

    // ---- Phase 1: fp32 values f_k(p*delta), p in [0, TE], into scratch ----
    for (int p = tid; p <= TE; p += blockDim.x) {
        float dv = (float)p * delta;
        float acc[HEADS];
        #pragma unroll
        for (int k = 0; k < HEADS; k++) acc[k] = __ldg(b2 + k);
        #pragma unroll 4
        for (int h = 0; h < HID; h++) {
            float s = silu_f(fmaf(dv, __ldg(w1 + h), __ldg(b1 + h)));
            const float* w2r = w2 + h * HEADS;
            #pragma unroll
            for (int k = 0; k < HEADS; k++) acc[k] = fmaf(s, __ldg(w2r + k), acc[k]);
        }
        #pragma unroll
        for (int k = 0; k < HEADS; k++) scratch[p * HEADS + k] = acc[k];
    }
    __syncthreads();

    // ---- Phase 2: pack half2(value, slope) rows ----
    for (int p = tid; p < TE; p += blockDim.x) {
        #pragma unroll
        for (int k = 0; k < HEADS; k++) {
            float v0 = scratch[p * HEADS + k];
            float v1 = scratch[(p + 1) * HEADS + k];
            __half2 h2 = __floats2half2_rn(v0, v1 - v0);
            tab[p * ROW_U32 + k] = *reinterpret_cast<unsigned int*>(&h2);
        }
    }
    __syncthreads();

    // ---- Phase 3: main loop. One thread = 4 consecutive j per iteration ----
    const float scale = (float)TE / DMAX_;
    const float tmax  = (float)TE - 0.001f;

    for (int g = blockIdx.x * blockDim.x + tid; g < ngroups; g += gridDim.x * blockDim.x) {
        int b  = g >> 18;               // 262144 groups per batch
        int r  = g & 262143;
        int i  = r >> 8;                // 256 j-groups per row
        int j0 = (r & 255) << 2;

        const float* cb = coords + b * (NPT * 3);
        float cix = cb[3 * i + 0];
        float ciy = cb[3 * i + 1];
        float ciz = cb[3 * i + 2];

        // 4 j's = 12 contiguous floats, 16B aligned (j0 % 4 == 0)
        const float4* cj4 = reinterpret_cast<const float4*>(cb + 3 * j0);
        float4 ca  = cj4[0];   // j0: x y z | j1: x
        float4 cbv = cj4[1];   // j1: y z | j2: x y
        float4 cc  = cj4[2];   // j2: z | j3: x y z

        float jx[4], jy[4], jz[4];
        jx[0] = ca.x;  jy[0] = ca.y;  jz[0] = ca.z;
        jx[1] = ca.w;  jy[1] = cbv.x; jz[1] = cbv.y;
        jx[2] = cbv.z; jy[2] = cbv.w; jz[2] = cc.x;
        jx[3] = cc.y;  jy[3] = cc.z;  jz[3] = cc.w;

        int   idx[4];
        float fr[4];
        #pragma unroll
        for (int u = 0; u < 4; u++) {
            float dx = cix - jx[u];
            float dy = ciy - jy[u];
            float dz = ciz - jz[u];
            float sq = fmaf(dx, dx, fmaf(dy, dy, dz * dz));
            float t  = fminf(sqrtf(sq) * scale, tmax);
            int  id  = (int)t;
            idx[u] = id * ROW_U32;
            fr[u]  = t - (float)id;
        }

        float* ob = out + (((size_t)(b * HEADS)) << 20) + ((size_t)i << 10) + j0;

        #pragma unroll
        for (int q = 0; q < 4; q++) {                 // head quad: heads 4q..4q+3
            uint4 u0 = *reinterpret_cast<const uint4*>(tab + idx[0] + q * 4);
            uint4 u1 = *reinterpret_cast<const uint4*>(tab + idx[1] + q * 4);
            uint4 u2 = *reinterpret_cast<const uint4*>(tab + idx[2] + q * 4);
            uint4 u3 = *reinterpret_cast<const uint4*>(tab + idx[3] + q * 4);

            unsigned int w0[4]  = {u0.x, u0.y, u0.z, u0.w};
            unsigned int w1r[4] = {u1.x, u1.y, u1.z, u1.w};
            unsigned int w2r[4] = {u2.x, u2.y, u2.z, u2.w};
            unsigned int w3[4]  = {u3.x, u3.y, u3.z, u3.w};

            #pragma unroll
            for (int hh = 0; hh < 4; hh++) {          // head within quad
                float2 f0 = __half22float2(*reinterpret_cast<__half2*>(&w0[hh]));
                float2 f1 = __half22float2(*reinterpret_cast<__half2*>(&w1r[hh]));
                float2 f2 = __half22float2(*reinterpret_cast<__half2*>(&w2r[hh]));
                float2 f3 = __half22float2(*reinterpret_cast<__half2*>(&w3[hh]));
                float4 v;
                v.x = fmaf(fr[0], f0.y, f0.x);
                v.y = fmaf(fr[1], f1.y, f1.x);
                v.z = fmaf(fr[2], f2.y, f2.x);
                v.w = fmaf(fr[3], f3.y, f3.x);
                int k = q * 4 + hh;
                __stcs(reinterpret_cast<float4*>(ob + ((size_t)k << 20)), v);
            }
        }
    }
}

extern "C" void kernel_launch(void* const* d_in, const int* in_sizes, int n_in,
                              void* d_out, int out_size)
{
    const float* coords = (const float*)d_in[0];
    const float* w1     = (const float*)d_in[1];
    const float* b1     = (const float*)d_in[2];
    const float* w2     = (const float*)d_in[3];
    const float* b2     = (const float*)d_in[4];
    float* out = (float*)d_out;

    const int smem_bytes = SCR_OFF * 4 + (TE + 1) * HEADS * 4;   // 81920 + 65600 = 147520
    cudaFuncSetAttribute(drb_kernel, cudaFuncAttributeMaxDynamicSharedMemorySize, smem_bytes);

    int nsm = 148;
    cudaDeviceGetAttribute(&nsm, cudaDevAttrMultiProcessorCount, 0);

    const int ngroups = NB * NPT * (NPT / 4);   // 1,048,576
    drb_kernel<<<nsm, 1024, smem_bytes>>>(coords, w1, b1, w2, b2, out, ngroups);
}